// round 1
// baseline (speedup 1.0000x reference)
#include <cuda_runtime.h>
#include <cuda_bf16.h>
#include <mma.h>
#include <math.h>

using namespace nvcuda;

#define DIM 2048
#define H 16
#define KVH 4
#define HD 128
#define RD 64
#define BATCH 4
#define T 2048
#define MTOT (BATCH * T)   // 8192
#define SCALE 0.08838834764831845f   // 128^-0.5
#define LOG2_10000 13.287712379549449f

// ---------------- scratch (device globals; no allocation allowed) -----------
__device__ float g_qlin[MTOT * DIM];        // x @ Wq^T           64 MB
__device__ float g_klin[MTOT * KVH * HD];   // x @ Wk^T           16 MB
__device__ float g_vlin[MTOT * KVH * HD];   // x @ Wv^T           16 MB
__device__ float g_q[BATCH * H * T * HD];   // rms+rope'd q       64 MB
__device__ float g_k[BATCH * KVH * T * HD]; // rms+rope'd k       16 MB
__device__ float g_v[BATCH * KVH * T * HD]; // reordered v        16 MB
__device__ float g_y[MTOT * DIM];           // attention out      64 MB

// ---------------- TF32 GEMM: C[M,N] = A[M,K] * B[N,K]^T ---------------------
// BM=128, BN=128, BK=32, 256 threads (8 warps, 2x4), warp tile 64x32.
#define CVT_TF32(f) { _Pragma("unroll") for (int _e = 0; _e < (f).num_elements; ++_e) (f).x[_e] = wmma::__float_to_tf32((f).x[_e]); }

__global__ void __launch_bounds__(256) gemm_tf32(
    const float* __restrict__ A, const float* __restrict__ B,
    float* __restrict__ C, int M, int N, int K)
{
    __shared__ float As[128 * 32];
    __shared__ float Bs[128 * 32];
    int tid = threadIdx.x;
    int warp = tid >> 5;
    int wm = warp >> 2, wn = warp & 3;
    int bm = blockIdx.y, bn = blockIdx.x;

    wmma::fragment<wmma::accumulator, 16, 16, 8, float> acc[4][2];
#pragma unroll
    for (int i = 0; i < 4; i++)
#pragma unroll
        for (int j = 0; j < 2; j++) wmma::fill_fragment(acc[i][j], 0.0f);

    const float* Ab = A + (size_t)bm * 128 * K;
    const float* Bb = B + (size_t)bn * 128 * K;

    for (int k0 = 0; k0 < K; k0 += 32) {
#pragma unroll
        for (int i = 0; i < 4; i++) {
            int idx = tid + i * 256;         // 1024 float4 per buffer
            int r = idx >> 3, c = idx & 7;
            ((float4*)As)[r * 8 + c] = ((const float4*)(Ab + (size_t)r * K + k0))[c];
            ((float4*)Bs)[r * 8 + c] = ((const float4*)(Bb + (size_t)r * K + k0))[c];
        }
        __syncthreads();
#pragma unroll
        for (int kk = 0; kk < 32; kk += 8) {
            wmma::fragment<wmma::matrix_a, 16, 16, 8, wmma::precision::tf32, wmma::row_major> a[4];
            wmma::fragment<wmma::matrix_b, 16, 16, 8, wmma::precision::tf32, wmma::col_major> bf[2];
#pragma unroll
            for (int i = 0; i < 4; i++) {
                wmma::load_matrix_sync(a[i], As + (wm * 64 + i * 16) * 32 + kk, 32);
                CVT_TF32(a[i]);
            }
#pragma unroll
            for (int j = 0; j < 2; j++) {
                wmma::load_matrix_sync(bf[j], Bs + (wn * 32 + j * 16) * 32 + kk, 32);
                CVT_TF32(bf[j]);
            }
#pragma unroll
            for (int i = 0; i < 4; i++)
#pragma unroll
                for (int j = 0; j < 2; j++)
                    wmma::mma_sync(acc[i][j], a[i], bf[j], acc[i][j]);
        }
        __syncthreads();
    }
#pragma unroll
    for (int i = 0; i < 4; i++)
#pragma unroll
        for (int j = 0; j < 2; j++)
            wmma::store_matrix_sync(
                C + (size_t)(bm * 128 + wm * 64 + i * 16) * N + bn * 128 + wn * 32 + j * 16,
                acc[i][j], N, wmma::mem_row_major);
}

// ---------------- RMSNorm + RoPE (+gain): one warp per head vector ----------
__global__ void rope_q_kernel(const float* __restrict__ qlin,
                              const float* __restrict__ gain,
                              float* __restrict__ qout)
{
    int w = (blockIdx.x * blockDim.x + threadIdx.x) >> 5;
    int lane = threadIdx.x & 31;
    int h = w % H;
    int t = (w / H) % T;
    int b = w / (H * T);

    const float* src = qlin + ((size_t)(b * T + t)) * DIM + h * HD;
    float v0 = src[lane], v1 = src[lane + 32], v2 = src[lane + 64], v3 = src[lane + 96];
    float ss = v0 * v0 + v1 * v1 + v2 * v2 + v3 * v3;
#pragma unroll
    for (int o = 16; o; o >>= 1) ss += __shfl_xor_sync(0xffffffffu, ss, o);
    float r = rsqrtf(ss * (1.0f / 128.0f) + 1e-6f);
    v0 *= r; v1 *= r; v2 *= r; v3 *= r;

    float inv = exp2f(-(float)lane * (LOG2_10000 / 32.0f));
    float fr = (float)t * inv;
    float sn, cs;
    sincosf(fr, &sn, &cs);
    float o0 = v0 * cs - v1 * sn;
    float o1 = v1 * cs + v0 * sn;

    float g = gain[h];
    float* dst = qout + (((size_t)(b * H + h)) * T + t) * HD;
    dst[lane]      = o0 * g;
    dst[lane + 32] = o1 * g;
    dst[lane + 64] = v2 * g;
    dst[lane + 96] = v3 * g;
}

__global__ void rope_k_kernel(const float* __restrict__ klin, float* __restrict__ kout)
{
    int w = (blockIdx.x * blockDim.x + threadIdx.x) >> 5;
    int lane = threadIdx.x & 31;
    int kv = w % KVH;
    int t = (w / KVH) % T;
    int b = w / (KVH * T);

    const float* src = klin + ((size_t)(b * T + t)) * (KVH * HD) + kv * HD;
    float v0 = src[lane], v1 = src[lane + 32], v2 = src[lane + 64], v3 = src[lane + 96];
    float ss = v0 * v0 + v1 * v1 + v2 * v2 + v3 * v3;
#pragma unroll
    for (int o = 16; o; o >>= 1) ss += __shfl_xor_sync(0xffffffffu, ss, o);
    float r = rsqrtf(ss * (1.0f / 128.0f) + 1e-6f);
    v0 *= r; v1 *= r; v2 *= r; v3 *= r;

    float inv = exp2f(-(float)lane * (LOG2_10000 / 32.0f));
    float fr = (float)t * inv;
    float sn, cs;
    sincosf(fr, &sn, &cs);
    float o0 = v0 * cs - v1 * sn;
    float o1 = v1 * cs + v0 * sn;

    float* dst = kout + (((size_t)(b * KVH + kv)) * T + t) * HD;
    dst[lane]      = o0;
    dst[lane + 32] = o1;
    dst[lane + 64] = v2;
    dst[lane + 96] = v3;
}

// v: [b*T+t][kv*HD+d] -> [b][kv][t][d]  (float4 granularity)
__global__ void v_reorder_kernel(const float* __restrict__ vlin, float* __restrict__ vout)
{
    int i4 = blockIdx.x * blockDim.x + threadIdx.x;   // over MTOT*512/4
    int d4 = i4 & 31;              // 32 float4 per 128-dim vector
    int kv = (i4 >> 5) & 3;
    int bt = i4 >> 7;
    int t = bt & (T - 1);
    int b = bt >> 11;
    float4 val = ((const float4*)vlin)[i4];
    ((float4*)(vout + (((size_t)(b * KVH + kv)) * T + t) * HD))[d4] = val;
}

// ---------------- Flash attention (BQ=64, BKV=64, 256 threads) --------------
// smem layout (bytes):
//  Qs   0      .. 32768   (64x128 f32)
//  Ks   32768  .. 65536   (64x128 f32)
//  Vs   65536  .. 98304   (64x128 f32)
//  Ss   98304  .. 116736  (64x72  f32)
//  Ps   116736 .. 133120  (64x64  f32)
//  Os   133120 .. 165888  (64x128 f32)
//  mrow 165888, lrow 166144, arow 166400 (64 f32 each) -> total 166656
#define FA_SMEM 166656

__global__ void __launch_bounds__(256) flash_kernel(
    const float* __restrict__ Q, const float* __restrict__ Kg,
    const float* __restrict__ Vg, const float* __restrict__ vlin,
    float* __restrict__ Y)
{
    extern __shared__ char sm[];
    float* Qs = (float*)sm;
    float* Ks = (float*)(sm + 32768);
    float* Vs = (float*)(sm + 65536);
    float* Ss = (float*)(sm + 98304);
    float* Ps = (float*)(sm + 116736);
    float* Os = (float*)(sm + 133120);
    float* mrow = (float*)(sm + 165888);
    float* lrow = (float*)(sm + 166144);
    float* arow = (float*)(sm + 166400);

    int tid = threadIdx.x;
    int warp = tid >> 5;
    int wm = warp >> 1, wn = warp & 1;
    int qi = blockIdx.x, h = blockIdx.y, b = blockIdx.z;
    int q0 = qi * 64;
    int kvh = h >> 2;

    const float* Qbase = Q + (((size_t)b * H + h) * T + q0) * HD;
    const float* Kbase = Kg + ((size_t)b * KVH + kvh) * T * HD;
    const float* Vbase = Vg + ((size_t)b * KVH + kvh) * T * HD;

    for (int i = tid; i < 2048; i += 256) {
        ((float4*)Qs)[i] = ((const float4*)Qbase)[i];
        ((float4*)Os)[i] = make_float4(0.f, 0.f, 0.f, 0.f);
    }
    if (tid < 64) { mrow[tid] = -INFINITY; lrow[tid] = 0.f; }

    for (int j = 0; j <= qi; j++) {
        __syncthreads();
        for (int i = tid; i < 2048; i += 256) {
            ((float4*)Ks)[i] = ((const float4*)Kbase)[(size_t)j * 2048 + i];
            ((float4*)Vs)[i] = ((const float4*)Vbase)[(size_t)j * 2048 + i];
        }
        __syncthreads();

        // S = Q @ K^T : warp (wm, wn) -> rows wm*16..+16, cols wn*32..+32
        {
            wmma::fragment<wmma::accumulator, 16, 16, 8, float> sacc[2];
            wmma::fill_fragment(sacc[0], 0.0f);
            wmma::fill_fragment(sacc[1], 0.0f);
#pragma unroll
            for (int kk = 0; kk < 128; kk += 8) {
                wmma::fragment<wmma::matrix_a, 16, 16, 8, wmma::precision::tf32, wmma::row_major> a;
                wmma::load_matrix_sync(a, Qs + wm * 16 * 128 + kk, 128);
                CVT_TF32(a);
#pragma unroll
                for (int n = 0; n < 2; n++) {
                    wmma::fragment<wmma::matrix_b, 16, 16, 8, wmma::precision::tf32, wmma::col_major> bb;
                    wmma::load_matrix_sync(bb, Ks + (wn * 32 + n * 16) * 128 + kk, 128);
                    CVT_TF32(bb);
                    wmma::mma_sync(sacc[n], a, bb, sacc[n]);
                }
            }
#pragma unroll
            for (int n = 0; n < 2; n++)
                wmma::store_matrix_sync(Ss + wm * 16 * 72 + wn * 32 + n * 16, sacc[n], 72,
                                        wmma::mem_row_major);
        }
        __syncthreads();

        // online softmax (one thread per row)
        if (tid < 64) {
            int r = tid;
            int qg = q0 + r;
            int kbase = j * 64;
            int cmax = qg - kbase; if (cmax > 63) cmax = 63;   // j<=qi => cmax>=0
            const float* srow = Ss + r * 72;
            float mold = mrow[r];
            float mx = -INFINITY;
            for (int c = 0; c <= cmax; c++) mx = fmaxf(mx, srow[c] * SCALE);
            float mnew = fmaxf(mold, mx);
            float alpha = __expf(mold - mnew);   // mold=-inf -> 0
            float sum = 0.f;
            float* prow = Ps + r * 64;
            for (int c = 0; c < 64; c++) {
                float p = (c <= cmax) ? __expf(srow[c] * SCALE - mnew) : 0.f;
                sum += p;
                prow[c] = p;
            }
            mrow[r] = mnew;
            lrow[r] = lrow[r] * alpha + sum;
            arow[r] = alpha;
        }
        __syncthreads();

        // rescale O
        for (int i = tid; i < 64 * 128; i += 256) Os[i] *= arow[i >> 7];
        __syncthreads();

        // O += P @ V : warp (wm, wn) -> rows wm*16..+16, cols wn*64..+64
        {
            wmma::fragment<wmma::accumulator, 16, 16, 8, float> oacc[4];
#pragma unroll
            for (int n = 0; n < 4; n++)
                wmma::load_matrix_sync(oacc[n], Os + wm * 16 * 128 + wn * 64 + n * 16, 128,
                                       wmma::mem_row_major);
#pragma unroll
            for (int kk = 0; kk < 64; kk += 8) {
                wmma::fragment<wmma::matrix_a, 16, 16, 8, wmma::precision::tf32, wmma::row_major> a;
                wmma::load_matrix_sync(a, Ps + wm * 16 * 64 + kk, 64);
                CVT_TF32(a);
#pragma unroll
                for (int n = 0; n < 4; n++) {
                    wmma::fragment<wmma::matrix_b, 16, 16, 8, wmma::precision::tf32, wmma::row_major> bb;
                    wmma::load_matrix_sync(bb, Vs + kk * 128 + wn * 64 + n * 16, 128);
                    CVT_TF32(bb);
                    wmma::mma_sync(oacc[n], a, bb, oacc[n]);
                }
            }
#pragma unroll
            for (int n = 0; n < 4; n++)
                wmma::store_matrix_sync(Os + wm * 16 * 128 + wn * 64 + n * 16, oacc[n], 128,
                                        wmma::mem_row_major);
        }
    }
    __syncthreads();

    // stage v rows (coalesced) into reused Qs region
    float* Vf = Qs;   // 64x128 f32 = 32 KB
    const float* vg = vlin + ((size_t)(b * T + q0)) * (KVH * HD) + kvh * HD;
    for (int i = tid; i < 64 * 32; i += 256) {
        int r = i >> 5, c = i & 31;
        ((float4*)(Vf + r * 128))[c] = ((const float4*)(vg + (size_t)r * (KVH * HD)))[c];
    }
    __syncthreads();

    // epilogue: /l, v-orthogonalize, transpose-store to [B,T,H*HD]
    if (tid < 64) {
        int r = tid;
        float invl = 1.0f / lrow[r];
        float sv2 = 0.f, dyv = 0.f;
        for (int dd = 0; dd < 128; dd++) {
            int d = (dd + r) & 127;    // bank-stagger
            float vv = Vf[r * 128 + d];
            float yy = Os[r * 128 + d] * invl;
            sv2 += vv * vv;
            dyv += yy * vv;
        }
        float nm = sqrtf(sv2);
        float mxn = fmaxf(nm, 1e-12f);
        float coef = dyv / (mxn * mxn);
        float* orow = Y + (((size_t)(b * T + q0 + r)) * H + h) * HD;
        for (int dd = 0; dd < 128; dd++) {
            int d = (dd + r) & 127;
            orow[d] = Os[r * 128 + d] * invl - coef * Vf[r * 128 + d];
        }
    }
}

// ---------------- launch ----------------------------------------------------
extern "C" void kernel_launch(void* const* d_in, const int* in_sizes, int n_in,
                              void* d_out, int out_size)
{
    const float* x    = (const float*)d_in[0];
    const float* Wq   = (const float*)d_in[1];
    const float* Wk   = (const float*)d_in[2];
    const float* Wv   = (const float*)d_in[3];
    const float* Wp   = (const float*)d_in[4];
    const float* gain = (const float*)d_in[5];

    float *qlin, *klin, *vlin, *q, *k, *v, *y;
    cudaGetSymbolAddress((void**)&qlin, g_qlin);
    cudaGetSymbolAddress((void**)&klin, g_klin);
    cudaGetSymbolAddress((void**)&vlin, g_vlin);
    cudaGetSymbolAddress((void**)&q, g_q);
    cudaGetSymbolAddress((void**)&k, g_k);
    cudaGetSymbolAddress((void**)&v, g_v);
    cudaGetSymbolAddress((void**)&y, g_y);

    // QKV projections
    gemm_tf32<<<dim3(DIM / 128, MTOT / 128), 256>>>(x, Wq, qlin, MTOT, DIM, DIM);
    gemm_tf32<<<dim3((KVH * HD) / 128, MTOT / 128), 256>>>(x, Wk, klin, MTOT, KVH * HD, DIM);
    gemm_tf32<<<dim3((KVH * HD) / 128, MTOT / 128), 256>>>(x, Wv, vlin, MTOT, KVH * HD, DIM);

    // rms+rope (+gain) and v reorder
    rope_q_kernel<<<(BATCH * T * H) / 4, 128>>>(qlin, gain, q);
    rope_k_kernel<<<(BATCH * T * KVH) / 4, 128>>>(klin, k);
    v_reorder_kernel<<<(MTOT * KVH * HD / 4) / 256, 256>>>(vlin, v);

    // flash attention + fused epilogue
    cudaFuncSetAttribute(flash_kernel, cudaFuncAttributeMaxDynamicSharedMemorySize, FA_SMEM);
    flash_kernel<<<dim3(T / 64, H, BATCH), 256, FA_SMEM>>>(q, k, v, vlin, y);

    // output projection
    gemm_tf32<<<dim3(DIM / 128, MTOT / 128), 256>>>(y, Wp, (float*)d_out, MTOT, DIM, DIM);
}

// round 2
// speedup vs baseline: 1.3430x; 1.3430x over previous
#include <cuda_runtime.h>
#include <cuda_bf16.h>
#include <mma.h>
#include <math.h>

using namespace nvcuda;

#define DIM 2048
#define H 16
#define KVH 4
#define HD 128
#define RD 64
#define BATCH 4
#define T 2048
#define MTOT (BATCH * T)   // 8192
#define SCALE 0.08838834764831845f   // 128^-0.5
#define LOG2_10000 13.287712379549449f

// ---------------- scratch (device globals; no allocation allowed) -----------
__device__ float g_qlin[MTOT * DIM];
__device__ float g_klin[MTOT * KVH * HD];
__device__ float g_vlin[MTOT * KVH * HD];
__device__ float g_q[BATCH * H * T * HD];
__device__ float g_k[BATCH * KVH * T * HD];
__device__ float g_v[BATCH * KVH * T * HD];
__device__ float g_y[MTOT * DIM];

// ---------------- cp.async helpers ------------------------------------------
__device__ __forceinline__ void cp_async16(void* smem, const void* gmem) {
    unsigned s = (unsigned)__cvta_generic_to_shared(smem);
    asm volatile("cp.async.cg.shared.global [%0], [%1], 16;\n" :: "r"(s), "l"(gmem) : "memory");
}
#define CP_COMMIT asm volatile("cp.async.commit_group;\n" ::: "memory")
#define CP_WAIT1  asm volatile("cp.async.wait_group 1;\n" ::: "memory")
#define CP_WAIT0  asm volatile("cp.async.wait_group 0;\n" ::: "memory")

#define CVT_TF32(f) { _Pragma("unroll") for (int _e = 0; _e < (f).num_elements; ++_e) (f).x[_e] = wmma::__float_to_tf32((f).x[_e]); }

// ---------------- TF32 GEMM: C[M,N] = A[M,K] * B[N,K]^T ---------------------
// BM=128, BN=128, BK=32, 256 threads, cp.async double buffered.
__global__ void __launch_bounds__(256) gemm_tf32(
    const float* __restrict__ A, const float* __restrict__ B,
    float* __restrict__ C, int M, int N, int K)
{
    extern __shared__ float smem[];
    float* As = smem;                  // 2 x 128x32
    float* Bs = smem + 2 * 128 * 32;   // 2 x 128x32
    int tid = threadIdx.x;
    int warp = tid >> 5;
    int wm = warp >> 2, wn = warp & 3;
    int bm = blockIdx.y, bn = blockIdx.x;

    wmma::fragment<wmma::accumulator, 16, 16, 8, float> acc[4][2];
#pragma unroll
    for (int i = 0; i < 4; i++)
#pragma unroll
        for (int j = 0; j < 2; j++) wmma::fill_fragment(acc[i][j], 0.0f);

    const float* Ab = A + (size_t)bm * 128 * K;
    const float* Bb = B + (size_t)bn * 128 * K;

    // prologue: tile 0 into buf 0
    {
#pragma unroll
        for (int i = 0; i < 4; i++) {
            int idx = tid + i * 256;
            int r = idx >> 3, c = (idx & 7) * 4;
            cp_async16(As + r * 32 + c, Ab + (size_t)r * K + c);
            cp_async16(Bs + r * 32 + c, Bb + (size_t)r * K + c);
        }
        CP_COMMIT;
    }

    int ntiles = K >> 5;
    for (int kt = 0; kt < ntiles; kt++) {
        int buf = kt & 1;
        float* Ab_s = As + buf * 4096;
        float* Bb_s = Bs + buf * 4096;
        if (kt + 1 < ntiles) {
            int k0 = (kt + 1) << 5;
            float* An = As + (buf ^ 1) * 4096;
            float* Bn = Bs + (buf ^ 1) * 4096;
#pragma unroll
            for (int i = 0; i < 4; i++) {
                int idx = tid + i * 256;
                int r = idx >> 3, c = (idx & 7) * 4;
                cp_async16(An + r * 32 + c, Ab + (size_t)r * K + k0 + c);
                cp_async16(Bn + r * 32 + c, Bb + (size_t)r * K + k0 + c);
            }
            CP_COMMIT;
            CP_WAIT1;
        } else {
            CP_WAIT0;
        }
        __syncthreads();
#pragma unroll
        for (int kk = 0; kk < 32; kk += 8) {
            wmma::fragment<wmma::matrix_a, 16, 16, 8, wmma::precision::tf32, wmma::row_major> a[4];
            wmma::fragment<wmma::matrix_b, 16, 16, 8, wmma::precision::tf32, wmma::col_major> bf[2];
#pragma unroll
            for (int i = 0; i < 4; i++) {
                wmma::load_matrix_sync(a[i], Ab_s + (wm * 64 + i * 16) * 32 + kk, 32);
                CVT_TF32(a[i]);
            }
#pragma unroll
            for (int j = 0; j < 2; j++) {
                wmma::load_matrix_sync(bf[j], Bb_s + (wn * 32 + j * 16) * 32 + kk, 32);
                CVT_TF32(bf[j]);
            }
#pragma unroll
            for (int i = 0; i < 4; i++)
#pragma unroll
                for (int j = 0; j < 2; j++)
                    wmma::mma_sync(acc[i][j], a[i], bf[j], acc[i][j]);
        }
        __syncthreads();
    }
#pragma unroll
    for (int i = 0; i < 4; i++)
#pragma unroll
        for (int j = 0; j < 2; j++)
            wmma::store_matrix_sync(
                C + (size_t)(bm * 128 + wm * 64 + i * 16) * N + bn * 128 + wn * 32 + j * 16,
                acc[i][j], N, wmma::mem_row_major);
}

// ---------------- RMSNorm + RoPE (+gain) ------------------------------------
__global__ void rope_q_kernel(const float* __restrict__ qlin,
                              const float* __restrict__ gain,
                              float* __restrict__ qout)
{
    int w = (blockIdx.x * blockDim.x + threadIdx.x) >> 5;
    int lane = threadIdx.x & 31;
    int h = w % H;
    int t = (w / H) % T;
    int b = w / (H * T);

    const float* src = qlin + ((size_t)(b * T + t)) * DIM + h * HD;
    float v0 = src[lane], v1 = src[lane + 32], v2 = src[lane + 64], v3 = src[lane + 96];
    float ss = v0 * v0 + v1 * v1 + v2 * v2 + v3 * v3;
#pragma unroll
    for (int o = 16; o; o >>= 1) ss += __shfl_xor_sync(0xffffffffu, ss, o);
    float r = rsqrtf(ss * (1.0f / 128.0f) + 1e-6f);
    v0 *= r; v1 *= r; v2 *= r; v3 *= r;

    float inv = exp2f(-(float)lane * (LOG2_10000 / 32.0f));
    float fr = (float)t * inv;
    float sn, cs;
    sincosf(fr, &sn, &cs);
    float o0 = v0 * cs - v1 * sn;
    float o1 = v1 * cs + v0 * sn;

    float g = gain[h];
    float* dst = qout + (((size_t)(b * H + h)) * T + t) * HD;
    dst[lane]      = o0 * g;
    dst[lane + 32] = o1 * g;
    dst[lane + 64] = v2 * g;
    dst[lane + 96] = v3 * g;
}

__global__ void rope_k_kernel(const float* __restrict__ klin, float* __restrict__ kout)
{
    int w = (blockIdx.x * blockDim.x + threadIdx.x) >> 5;
    int lane = threadIdx.x & 31;
    int kv = w % KVH;
    int t = (w / KVH) % T;
    int b = w / (KVH * T);

    const float* src = klin + ((size_t)(b * T + t)) * (KVH * HD) + kv * HD;
    float v0 = src[lane], v1 = src[lane + 32], v2 = src[lane + 64], v3 = src[lane + 96];
    float ss = v0 * v0 + v1 * v1 + v2 * v2 + v3 * v3;
#pragma unroll
    for (int o = 16; o; o >>= 1) ss += __shfl_xor_sync(0xffffffffu, ss, o);
    float r = rsqrtf(ss * (1.0f / 128.0f) + 1e-6f);
    v0 *= r; v1 *= r; v2 *= r; v3 *= r;

    float inv = exp2f(-(float)lane * (LOG2_10000 / 32.0f));
    float fr = (float)t * inv;
    float sn, cs;
    sincosf(fr, &sn, &cs);
    float o0 = v0 * cs - v1 * sn;
    float o1 = v1 * cs + v0 * sn;

    float* dst = kout + (((size_t)(b * KVH + kv)) * T + t) * HD;
    dst[lane]      = o0;
    dst[lane + 32] = o1;
    dst[lane + 64] = v2;
    dst[lane + 96] = v3;
}

__global__ void v_reorder_kernel(const float* __restrict__ vlin, float* __restrict__ vout)
{
    int i4 = blockIdx.x * blockDim.x + threadIdx.x;
    int d4 = i4 & 31;
    int kv = (i4 >> 5) & 3;
    int bt = i4 >> 7;
    int t = bt & (T - 1);
    int b = bt >> 11;
    float4 val = ((const float4*)vlin)[i4];
    ((float4*)(vout + (((size_t)(b * KVH + kv)) * T + t) * HD))[d4] = val;
}

// ---------------- Flash attention (BQ=64, BKV=64, 256 threads) --------------
// smem: Qs 0..32K | Os 32K..64K | Ks[2] 64K..128K | Vs[2] 128K..192K |
//       SP 192K..210K (64x72) | mrow/lrow/arow
#define FA_SMEM (215040 + 768)

__global__ void __launch_bounds__(256) flash_kernel(
    const float* __restrict__ Q, const float* __restrict__ Kg,
    const float* __restrict__ Vg, const float* __restrict__ vlin,
    float* __restrict__ Y)
{
    extern __shared__ char sm[];
    float* Qs  = (float*)sm;
    float* Os  = (float*)(sm + 32768);
    float* Ksm = (float*)(sm + 65536);
    float* Vsm = (float*)(sm + 131072);
    float* SP  = (float*)(sm + 196608);
    float* mrow = (float*)(sm + 215040);
    float* lrow = (float*)(sm + 215296);
    float* arow = (float*)(sm + 215552);

    const int tid = threadIdx.x;
    const int warp = tid >> 5;
    const int wm = warp >> 1, wn = warp & 1;
    const int qi = blockIdx.x, h = blockIdx.y, b = blockIdx.z;
    const int q0 = qi * 64;
    const int kvh = h >> 2;

    const float* Qbase = Q + (((size_t)b * H + h) * T + q0) * HD;
    const float* Kbase = Kg + ((size_t)b * KVH + kvh) * T * HD;
    const float* Vbase = Vg + ((size_t)b * KVH + kvh) * T * HD;

    // prologue: async load of KV tile 0
    {
        const float4* Kg4 = (const float4*)Kbase;
        const float4* Vg4 = (const float4*)Vbase;
#pragma unroll
        for (int i = 0; i < 8; i++) {
            int idx = tid + i * 256;
            cp_async16((float4*)Ksm + idx, Kg4 + idx);
            cp_async16((float4*)Vsm + idx, Vg4 + idx);
        }
        CP_COMMIT;
    }

    // Q (pre-scaled) + zero O
    for (int i = tid; i < 2048; i += 256) {
        float4 qv = ((const float4*)Qbase)[i];
        qv.x *= SCALE; qv.y *= SCALE; qv.z *= SCALE; qv.w *= SCALE;
        ((float4*)Qs)[i] = qv;
        ((float4*)Os)[i] = make_float4(0.f, 0.f, 0.f, 0.f);
    }
    if (tid < 64) { mrow[tid] = -INFINITY; lrow[tid] = 0.f; }

    for (int j = 0; j <= qi; j++) {
        const int buf = j & 1;
        float* Ks = Ksm + buf * 8192;
        float* Vs = Vsm + buf * 8192;
        if (j < qi) {
            const float4* Kg4 = (const float4*)(Kbase + (size_t)(j + 1) * 8192);
            const float4* Vg4 = (const float4*)(Vbase + (size_t)(j + 1) * 8192);
            float* Kn = Ksm + (buf ^ 1) * 8192;
            float* Vn = Vsm + (buf ^ 1) * 8192;
#pragma unroll
            for (int i = 0; i < 8; i++) {
                int idx = tid + i * 256;
                cp_async16((float4*)Kn + idx, Kg4 + idx);
                cp_async16((float4*)Vn + idx, Vg4 + idx);
            }
            CP_COMMIT;
            CP_WAIT1;
        } else {
            CP_WAIT0;
        }
        __syncthreads();

        // S = Q @ K^T  (warp (wm,wn): rows wm*16, cols wn*32)
        {
            wmma::fragment<wmma::accumulator, 16, 16, 8, float> sacc[2];
            wmma::fill_fragment(sacc[0], 0.0f);
            wmma::fill_fragment(sacc[1], 0.0f);
#pragma unroll
            for (int kk = 0; kk < 128; kk += 8) {
                wmma::fragment<wmma::matrix_a, 16, 16, 8, wmma::precision::tf32, wmma::row_major> a;
                wmma::load_matrix_sync(a, Qs + wm * 16 * 128 + kk, 128);
                CVT_TF32(a);
#pragma unroll
                for (int n = 0; n < 2; n++) {
                    wmma::fragment<wmma::matrix_b, 16, 16, 8, wmma::precision::tf32, wmma::col_major> bb;
                    wmma::load_matrix_sync(bb, Ks + (wn * 32 + n * 16) * 128 + kk, 128);
                    CVT_TF32(bb);
                    wmma::mma_sync(sacc[n], a, bb, sacc[n]);
                }
            }
#pragma unroll
            for (int n = 0; n < 2; n++)
                wmma::store_matrix_sync(SP + wm * 16 * 72 + wn * 32 + n * 16, sacc[n], 72,
                                        wmma::mem_row_major);
        }
        __syncthreads();

        // online softmax: 4 threads per row, in-place exp in SP
        {
            const int r = tid >> 2, sub = tid & 3;
            float* srow = SP + r * 72 + sub * 16;
            float mold = mrow[r];
            float mx = -INFINITY;
            if (j == qi) {
                // diagonal block: col c valid iff sub*16+c <= r
#pragma unroll
                for (int c = 0; c < 16; c++)
                    if (sub * 16 + c <= r) mx = fmaxf(mx, srow[c]);
            } else {
#pragma unroll
                for (int c = 0; c < 16; c++) mx = fmaxf(mx, srow[c]);
            }
            mx = fmaxf(mx, __shfl_xor_sync(0xffffffffu, mx, 1));
            mx = fmaxf(mx, __shfl_xor_sync(0xffffffffu, mx, 2));
            float mnew = fmaxf(mold, mx);
            float alpha = __expf(mold - mnew);
            float sum = 0.f;
            if (j == qi) {
#pragma unroll
                for (int c = 0; c < 16; c++) {
                    float p = (sub * 16 + c <= r) ? __expf(srow[c] - mnew) : 0.f;
                    sum += p;
                    srow[c] = p;
                }
            } else {
#pragma unroll
                for (int c = 0; c < 16; c++) {
                    float p = __expf(srow[c] - mnew);
                    sum += p;
                    srow[c] = p;
                }
            }
            sum += __shfl_xor_sync(0xffffffffu, sum, 1);
            sum += __shfl_xor_sync(0xffffffffu, sum, 2);
            if (sub == 0) {
                mrow[r] = mnew;
                lrow[r] = lrow[r] * alpha + sum;
                arow[r] = alpha;
            }
        }
        __syncthreads();

        // rescale O
        for (int i = tid; i < 2048; i += 256) {
            float a = arow[i >> 5];
            float4 o = ((float4*)Os)[i];
            o.x *= a; o.y *= a; o.z *= a; o.w *= a;
            ((float4*)Os)[i] = o;
        }
        __syncthreads();

        // O += P @ V  (warp (wm,wn): rows wm*16, cols wn*64)
        {
            wmma::fragment<wmma::accumulator, 16, 16, 8, float> oacc[4];
#pragma unroll
            for (int n = 0; n < 4; n++)
                wmma::load_matrix_sync(oacc[n], Os + wm * 16 * 128 + wn * 64 + n * 16, 128,
                                       wmma::mem_row_major);
#pragma unroll
            for (int kk = 0; kk < 64; kk += 8) {
                wmma::fragment<wmma::matrix_a, 16, 16, 8, wmma::precision::tf32, wmma::row_major> a;
                wmma::load_matrix_sync(a, SP + wm * 16 * 72 + kk, 72);
                CVT_TF32(a);
#pragma unroll
                for (int n = 0; n < 4; n++) {
                    wmma::fragment<wmma::matrix_b, 16, 16, 8, wmma::precision::tf32, wmma::row_major> bb;
                    wmma::load_matrix_sync(bb, Vs + kk * 128 + wn * 64 + n * 16, 128);
                    CVT_TF32(bb);
                    wmma::mma_sync(oacc[n], a, bb, oacc[n]);
                }
            }
#pragma unroll
            for (int n = 0; n < 4; n++)
                wmma::store_matrix_sync(Os + wm * 16 * 128 + wn * 64 + n * 16, oacc[n], 128,
                                        wmma::mem_row_major);
        }
        __syncthreads();
    }

    // stage per-position v rows into reused Qs
    float* Vf = Qs;
    const float* vg = vlin + ((size_t)(b * T + q0)) * (KVH * HD) + kvh * HD;
    for (int i = tid; i < 64 * 32; i += 256) {
        int r = i >> 5, c = i & 31;
        ((float4*)(Vf + r * 128))[c] = ((const float4*)(vg + (size_t)r * (KVH * HD)))[c];
    }
    __syncthreads();

    // epilogue: /l, v-orthogonalize, transpose-store  (4 threads per row)
    {
        const int r = tid >> 2, sub = tid & 3;
        float invl = 1.0f / lrow[r];
        const float4* v4 = (const float4*)(Vf + r * 128 + sub * 32);
        const float4* o4 = (const float4*)(Os + r * 128 + sub * 32);
        float sv2 = 0.f, dyv = 0.f;
#pragma unroll
        for (int cc = 0; cc < 8; cc++) {
            int c = (cc + r) & 7;   // bank stagger
            float4 vv = v4[c];
            float4 yy = o4[c];
            sv2 += vv.x * vv.x + vv.y * vv.y + vv.z * vv.z + vv.w * vv.w;
            dyv += yy.x * vv.x + yy.y * vv.y + yy.z * vv.z + yy.w * vv.w;
        }
        sv2 += __shfl_xor_sync(0xffffffffu, sv2, 1);
        sv2 += __shfl_xor_sync(0xffffffffu, sv2, 2);
        dyv += __shfl_xor_sync(0xffffffffu, dyv, 1);
        dyv += __shfl_xor_sync(0xffffffffu, dyv, 2);
        float nm = fmaxf(sqrtf(sv2), 1e-12f);
        float coef = (dyv * invl) / (nm * nm);
        float4* out4 = (float4*)(Y + (((size_t)(b * T + q0 + r)) * H + h) * HD + sub * 32);
#pragma unroll
        for (int cc = 0; cc < 8; cc++) {
            int c = (cc + r) & 7;
            float4 vv = v4[c];
            float4 yy = o4[c];
            float4 o;
            o.x = yy.x * invl - coef * vv.x;
            o.y = yy.y * invl - coef * vv.y;
            o.z = yy.z * invl - coef * vv.z;
            o.w = yy.w * invl - coef * vv.w;
            out4[c] = o;
        }
    }
}

// ---------------- launch ----------------------------------------------------
extern "C" void kernel_launch(void* const* d_in, const int* in_sizes, int n_in,
                              void* d_out, int out_size)
{
    const float* x    = (const float*)d_in[0];
    const float* Wq   = (const float*)d_in[1];
    const float* Wk   = (const float*)d_in[2];
    const float* Wv   = (const float*)d_in[3];
    const float* Wp   = (const float*)d_in[4];
    const float* gain = (const float*)d_in[5];

    float *qlin, *klin, *vlin, *q, *k, *v, *y;
    cudaGetSymbolAddress((void**)&qlin, g_qlin);
    cudaGetSymbolAddress((void**)&klin, g_klin);
    cudaGetSymbolAddress((void**)&vlin, g_vlin);
    cudaGetSymbolAddress((void**)&q, g_q);
    cudaGetSymbolAddress((void**)&k, g_k);
    cudaGetSymbolAddress((void**)&v, g_v);
    cudaGetSymbolAddress((void**)&y, g_y);

    static bool attr_done = false;
    if (!attr_done) {
        cudaFuncSetAttribute(gemm_tf32, cudaFuncAttributeMaxDynamicSharedMemorySize, 65536);
        cudaFuncSetAttribute(flash_kernel, cudaFuncAttributeMaxDynamicSharedMemorySize, FA_SMEM);
        attr_done = true;
    }

    // QKV projections
    gemm_tf32<<<dim3(DIM / 128, MTOT / 128), 256, 65536>>>(x, Wq, qlin, MTOT, DIM, DIM);
    gemm_tf32<<<dim3((KVH * HD) / 128, MTOT / 128), 256, 65536>>>(x, Wk, klin, MTOT, KVH * HD, DIM);
    gemm_tf32<<<dim3((KVH * HD) / 128, MTOT / 128), 256, 65536>>>(x, Wv, vlin, MTOT, KVH * HD, DIM);

    // rms+rope (+gain) and v reorder
    rope_q_kernel<<<(BATCH * T * H) / 4, 128>>>(qlin, gain, q);
    rope_k_kernel<<<(BATCH * T * KVH) / 4, 128>>>(klin, k);
    v_reorder_kernel<<<(MTOT * KVH * HD / 4) / 256, 256>>>(vlin, v);

    // flash attention + fused epilogue
    flash_kernel<<<dim3(T / 64, H, BATCH), 256, FA_SMEM>>>(q, k, v, vlin, y);

    // output projection
    gemm_tf32<<<dim3(DIM / 128, MTOT / 128), 256, 65536>>>(y, Wp, (float*)d_out, MTOT, DIM, DIM);
}

// round 3
// speedup vs baseline: 1.4886x; 1.1084x over previous
#include <cuda_runtime.h>
#include <cuda_bf16.h>
#include <mma.h>
#include <math.h>

using namespace nvcuda;

#define DIM 2048
#define H 16
#define KVH 4
#define HD 128
#define RD 64
#define BATCH 4
#define T 2048
#define MTOT (BATCH * T)   // 8192
#define SCALE 0.08838834764831845f   // 128^-0.5
#define LOG2_10000 13.287712379549449f

// ---------------- scratch (device globals; no allocation allowed) -----------
__device__ float g_qlin[MTOT * DIM];
__device__ float g_klin[MTOT * KVH * HD];
__device__ float g_vlin[MTOT * KVH * HD];
__device__ float g_q[BATCH * H * T * HD];
__device__ float g_k[BATCH * KVH * T * HD];
__device__ float g_v[BATCH * KVH * T * HD];
__device__ float g_y[MTOT * DIM];
// tf32-truncated copies of GEMM operands
__device__ float g_xt[MTOT * DIM];
__device__ float g_wqt[DIM * DIM];
__device__ float g_wkt[KVH * HD * DIM];
__device__ float g_wvt[KVH * HD * DIM];
__device__ float g_wpt[DIM * DIM];

// ---------------- helpers ----------------------------------------------------
__device__ __forceinline__ float to_tf32(float x) {
    float r;
    asm("cvt.rna.tf32.f32 %0, %1;\n" : "=f"(r) : "f"(x));
    return r;
}
__device__ __forceinline__ void cp_async16(void* smem, const void* gmem) {
    unsigned s = (unsigned)__cvta_generic_to_shared(smem);
    asm volatile("cp.async.cg.shared.global [%0], [%1], 16;\n" :: "r"(s), "l"(gmem) : "memory");
}
#define CP_COMMIT asm volatile("cp.async.commit_group;\n" ::: "memory")
#define CP_WAIT0  asm volatile("cp.async.wait_group 0;\n" ::: "memory")
#define CP_WAIT1  asm volatile("cp.async.wait_group 1;\n" ::: "memory")
#define CP_WAIT2  asm volatile("cp.async.wait_group 2;\n" ::: "memory")

// tf32 truncation pass (RN) — idempotent elementwise copy
__global__ void tf32_convert(const float* __restrict__ src, float* __restrict__ dst, int n4)
{
    int i = blockIdx.x * blockDim.x + threadIdx.x;
    if (i < n4) {
        float4 v = ((const float4*)src)[i];
        v.x = to_tf32(v.x); v.y = to_tf32(v.y);
        v.z = to_tf32(v.z); v.w = to_tf32(v.w);
        ((float4*)dst)[i] = v;
    }
}

// ---------------- TF32 GEMM: C[M,N] = A[M,K] * B[N,K]^T ---------------------
// inputs pre-truncated to tf32. BM=128 BN=128 BK=32, 256 thr, double-buffered.
__global__ void __launch_bounds__(256) gemm_tf32(
    const float* __restrict__ A, const float* __restrict__ B,
    float* __restrict__ C, int M, int N, int K)
{
    extern __shared__ float smem[];
    float* As = smem;
    float* Bs = smem + 2 * 128 * 32;
    int tid = threadIdx.x;
    int warp = tid >> 5;
    int wm = warp >> 2, wn = warp & 3;
    int bm = blockIdx.y, bn = blockIdx.x;

    wmma::fragment<wmma::accumulator, 16, 16, 8, float> acc[4][2];
#pragma unroll
    for (int i = 0; i < 4; i++)
#pragma unroll
        for (int j = 0; j < 2; j++) wmma::fill_fragment(acc[i][j], 0.0f);

    const float* Ab = A + (size_t)bm * 128 * K;
    const float* Bb = B + (size_t)bn * 128 * K;

    {
#pragma unroll
        for (int i = 0; i < 4; i++) {
            int idx = tid + i * 256;
            int r = idx >> 3, c = (idx & 7) * 4;
            cp_async16(As + r * 32 + c, Ab + (size_t)r * K + c);
            cp_async16(Bs + r * 32 + c, Bb + (size_t)r * K + c);
        }
        CP_COMMIT;
    }

    int ntiles = K >> 5;
    for (int kt = 0; kt < ntiles; kt++) {
        int buf = kt & 1;
        float* Ab_s = As + buf * 4096;
        float* Bb_s = Bs + buf * 4096;
        if (kt + 1 < ntiles) {
            int k0 = (kt + 1) << 5;
            float* An = As + (buf ^ 1) * 4096;
            float* Bn = Bs + (buf ^ 1) * 4096;
#pragma unroll
            for (int i = 0; i < 4; i++) {
                int idx = tid + i * 256;
                int r = idx >> 3, c = (idx & 7) * 4;
                cp_async16(An + r * 32 + c, Ab + (size_t)r * K + k0 + c);
                cp_async16(Bn + r * 32 + c, Bb + (size_t)r * K + k0 + c);
            }
            CP_COMMIT;
            CP_WAIT1;
        } else {
            CP_WAIT0;
        }
        __syncthreads();
#pragma unroll
        for (int kk = 0; kk < 32; kk += 8) {
            wmma::fragment<wmma::matrix_a, 16, 16, 8, wmma::precision::tf32, wmma::row_major> a[4];
            wmma::fragment<wmma::matrix_b, 16, 16, 8, wmma::precision::tf32, wmma::col_major> bf[2];
#pragma unroll
            for (int i = 0; i < 4; i++)
                wmma::load_matrix_sync(a[i], Ab_s + (wm * 64 + i * 16) * 32 + kk, 32);
#pragma unroll
            for (int j = 0; j < 2; j++)
                wmma::load_matrix_sync(bf[j], Bb_s + (wn * 32 + j * 16) * 32 + kk, 32);
#pragma unroll
            for (int i = 0; i < 4; i++)
#pragma unroll
                for (int j = 0; j < 2; j++)
                    wmma::mma_sync(acc[i][j], a[i], bf[j], acc[i][j]);
        }
        __syncthreads();
    }
#pragma unroll
    for (int i = 0; i < 4; i++)
#pragma unroll
        for (int j = 0; j < 2; j++)
            wmma::store_matrix_sync(
                C + (size_t)(bm * 128 + wm * 64 + i * 16) * N + bn * 128 + wn * 32 + j * 16,
                acc[i][j], N, wmma::mem_row_major);
}

// ---------------- RMSNorm + RoPE (+gain+scale), tf32 output ------------------
__global__ void rope_q_kernel(const float* __restrict__ qlin,
                              const float* __restrict__ gain,
                              float* __restrict__ qout)
{
    int w = (blockIdx.x * blockDim.x + threadIdx.x) >> 5;
    int lane = threadIdx.x & 31;
    int h = w % H;
    int t = (w / H) % T;
    int b = w / (H * T);

    const float* src = qlin + ((size_t)(b * T + t)) * DIM + h * HD;
    float v0 = src[lane], v1 = src[lane + 32], v2 = src[lane + 64], v3 = src[lane + 96];
    float ss = v0 * v0 + v1 * v1 + v2 * v2 + v3 * v3;
#pragma unroll
    for (int o = 16; o; o >>= 1) ss += __shfl_xor_sync(0xffffffffu, ss, o);
    float r = rsqrtf(ss * (1.0f / 128.0f) + 1e-6f);
    v0 *= r; v1 *= r; v2 *= r; v3 *= r;

    float inv = exp2f(-(float)lane * (LOG2_10000 / 32.0f));
    float fr = (float)t * inv;
    float sn, cs;
    sincosf(fr, &sn, &cs);
    float o0 = v0 * cs - v1 * sn;
    float o1 = v1 * cs + v0 * sn;

    float g = gain[h] * SCALE;
    float* dst = qout + (((size_t)(b * H + h)) * T + t) * HD;
    dst[lane]      = to_tf32(o0 * g);
    dst[lane + 32] = to_tf32(o1 * g);
    dst[lane + 64] = to_tf32(v2 * g);
    dst[lane + 96] = to_tf32(v3 * g);
}

__global__ void rope_k_kernel(const float* __restrict__ klin, float* __restrict__ kout)
{
    int w = (blockIdx.x * blockDim.x + threadIdx.x) >> 5;
    int lane = threadIdx.x & 31;
    int kv = w % KVH;
    int t = (w / KVH) % T;
    int b = w / (KVH * T);

    const float* src = klin + ((size_t)(b * T + t)) * (KVH * HD) + kv * HD;
    float v0 = src[lane], v1 = src[lane + 32], v2 = src[lane + 64], v3 = src[lane + 96];
    float ss = v0 * v0 + v1 * v1 + v2 * v2 + v3 * v3;
#pragma unroll
    for (int o = 16; o; o >>= 1) ss += __shfl_xor_sync(0xffffffffu, ss, o);
    float r = rsqrtf(ss * (1.0f / 128.0f) + 1e-6f);
    v0 *= r; v1 *= r; v2 *= r; v3 *= r;

    float inv = exp2f(-(float)lane * (LOG2_10000 / 32.0f));
    float fr = (float)t * inv;
    float sn, cs;
    sincosf(fr, &sn, &cs);
    float o0 = v0 * cs - v1 * sn;
    float o1 = v1 * cs + v0 * sn;

    float* dst = kout + (((size_t)(b * KVH + kv)) * T + t) * HD;
    dst[lane]      = to_tf32(o0);
    dst[lane + 32] = to_tf32(o1);
    dst[lane + 64] = to_tf32(v2);
    dst[lane + 96] = to_tf32(v3);
}

__global__ void v_reorder_kernel(const float* __restrict__ vlin, float* __restrict__ vout)
{
    int i4 = blockIdx.x * blockDim.x + threadIdx.x;
    int d4 = i4 & 31;
    int kv = (i4 >> 5) & 3;
    int bt = i4 >> 7;
    int t = bt & (T - 1);
    int b = bt >> 11;
    float4 val = ((const float4*)vlin)[i4];
    val.x = to_tf32(val.x); val.y = to_tf32(val.y);
    val.z = to_tf32(val.z); val.w = to_tf32(val.w);
    ((float4*)(vout + (((size_t)(b * KVH + kv)) * T + t) * HD))[d4] = val;
}

// ---------------- Flash attention (BQ=128, BKV=64, 256 threads) -------------
// smem bytes:
//  Qs   0      .. 65536   (128x128 f32)
//  Ksm  65536  .. 131072  (2 x 64x128)  — reused as Osm (128x128) after loop
//  Vsm  131072 .. 196608  (2 x 64x128)
//  SP   196608 .. 231424  (128 x 68 f32)
//  arow 231424 .. 231936  (128 f32) — alpha during loop, l after
#define FA_SMEM 231936

__global__ void __launch_bounds__(256) flash_kernel(
    const float* __restrict__ Q, const float* __restrict__ Kg,
    const float* __restrict__ Vg, const float* __restrict__ vlin,
    float* __restrict__ Y)
{
    extern __shared__ char sm[];
    float* Qs   = (float*)sm;
    float* Ksm  = (float*)(sm + 65536);
    float* Vsm  = (float*)(sm + 131072);
    float* SP   = (float*)(sm + 196608);
    float* arow = (float*)(sm + 231424);
    float* Osm  = Ksm;   // reuse after loop

    const int tid = threadIdx.x;
    const int warp = tid >> 5;
    const int wm = warp >> 1, wn = warp & 1;   // wm: 32-row tile, wn: 64-col tile
    const int qi = blockIdx.x, h = blockIdx.y, b = blockIdx.z;
    const int q0 = qi * 128;
    const int kvh = h >> 2;
    const int njt = 2 * qi + 2;

    const float* Qbase = Q + (((size_t)b * H + h) * T + q0) * HD;
    const float* Kbase = Kg + ((size_t)b * KVH + kvh) * T * HD;
    const float* Vbase = Vg + ((size_t)b * KVH + kvh) * T * HD;

    // prologue: K0 (group), V0 (group)
#pragma unroll
    for (int i = 0; i < 8; i++)
        cp_async16((float4*)Ksm + tid + i * 256, (const float4*)Kbase + tid + i * 256);
    CP_COMMIT;
#pragma unroll
    for (int i = 0; i < 8; i++)
        cp_async16((float4*)Vsm + tid + i * 256, (const float4*)Vbase + tid + i * 256);
    CP_COMMIT;

    // Q copy (pre-scaled, tf32) + probe pattern for accumulator row map
    for (int i = tid; i < 4096; i += 256)
        ((float4*)Qs)[i] = ((const float4*)Qbase)[i];
    {
        int r = tid >> 4, c = tid & 15;
        SP[r * 68 + c] = (float)r;
    }
    __syncthreads();

    int rowmap[8];
    {
        wmma::fragment<wmma::accumulator, 16, 16, 8, float> probe;
        wmma::load_matrix_sync(probe, SP, 68, wmma::mem_row_major);
#pragma unroll
        for (int e = 0; e < 8; e++) rowmap[e] = (int)probe.x[e];
    }

    wmma::fragment<wmma::accumulator, 16, 16, 8, float> oacc[2][4];
#pragma unroll
    for (int i = 0; i < 2; i++)
#pragma unroll
        for (int n = 0; n < 4; n++) wmma::fill_fragment(oacc[i][n], 0.0f);

    const int r_sm = tid >> 1, sub = tid & 1;   // softmax: 2 threads per row
    float m_state = -INFINITY, l_state = 0.f;

    for (int j = 0; j < njt; j++) {
        const int buf = j & 1;
        float* Ks = Ksm + buf * 8192;
        float* Vs = Vsm + buf * 8192;
        const int kbase = j * 64;

        if (j + 1 < njt) {
            float* Kn = Ksm + (buf ^ 1) * 8192;
            const float4* Kg4 = (const float4*)(Kbase + (size_t)(j + 1) * 8192);
#pragma unroll
            for (int i = 0; i < 8; i++)
                cp_async16((float4*)Kn + tid + i * 256, Kg4 + tid + i * 256);
            CP_COMMIT;
            CP_WAIT2;
        } else {
            CP_WAIT1;
        }
        __syncthreads();   // K tile visible; SP free for reuse

        // S = Q @ K^T : warp -> rows [wm*32, +32), cols [wn*32, +32)
        {
            wmma::fragment<wmma::accumulator, 16, 16, 8, float> sacc[2][2];
#pragma unroll
            for (int i = 0; i < 2; i++)
#pragma unroll
                for (int n = 0; n < 2; n++) wmma::fill_fragment(sacc[i][n], 0.0f);
#pragma unroll
            for (int kk = 0; kk < 128; kk += 8) {
                wmma::fragment<wmma::matrix_a, 16, 16, 8, wmma::precision::tf32, wmma::row_major> a[2];
                wmma::fragment<wmma::matrix_b, 16, 16, 8, wmma::precision::tf32, wmma::col_major> bb[2];
#pragma unroll
                for (int i = 0; i < 2; i++)
                    wmma::load_matrix_sync(a[i], Qs + (wm * 32 + i * 16) * 128 + kk, 128);
#pragma unroll
                for (int n = 0; n < 2; n++)
                    wmma::load_matrix_sync(bb[n], Ks + (wn * 32 + n * 16) * 128 + kk, 128);
#pragma unroll
                for (int i = 0; i < 2; i++)
#pragma unroll
                    for (int n = 0; n < 2; n++)
                        wmma::mma_sync(sacc[i][n], a[i], bb[n], sacc[i][n]);
            }
#pragma unroll
            for (int i = 0; i < 2; i++)
#pragma unroll
                for (int n = 0; n < 2; n++)
                    wmma::store_matrix_sync(SP + (wm * 32 + i * 16) * 68 + wn * 32 + n * 16,
                                            sacc[i][n], 68, wmma::mem_row_major);
        }
        __syncthreads();

        // online softmax: 2 threads per row, 32 cols each, state in registers
        {
            float* srow = SP + r_sm * 68 + sub * 32;
            int lim = q0 + r_sm - kbase - sub * 32;   // valid c <= lim
            float mx = -INFINITY;
#pragma unroll
            for (int c = 0; c < 32; c++)
                if (c <= lim) mx = fmaxf(mx, srow[c]);
            mx = fmaxf(mx, __shfl_xor_sync(0xffffffffu, mx, 1));
            float mnew = fmaxf(m_state, mx);
            float alpha = __expf(m_state - mnew);
            float sum = 0.f;
#pragma unroll
            for (int c = 0; c < 32; c++) {
                float p = (c <= lim) ? __expf(srow[c] - mnew) : 0.f;
                sum += p;
                srow[c] = to_tf32(p);
            }
            sum += __shfl_xor_sync(0xffffffffu, sum, 1);
            m_state = mnew;
            l_state = l_state * alpha + sum;
            if (sub == 0) arow[r_sm] = alpha;
        }
        __syncthreads();

        // prefetch next V
        if (j + 1 < njt) {
            float* Vn = Vsm + (buf ^ 1) * 8192;
            const float4* Vg4 = (const float4*)(Vbase + (size_t)(j + 1) * 8192);
#pragma unroll
            for (int i = 0; i < 8; i++)
                cp_async16((float4*)Vn + tid + i * 256, Vg4 + tid + i * 256);
            CP_COMMIT;
            CP_WAIT2;
        } else {
            CP_WAIT0;
        }
        __syncthreads();   // V_j visible

        // rescale O in registers, then O += P @ V
        {
#pragma unroll
            for (int i = 0; i < 2; i++) {
                float al[8];
#pragma unroll
                for (int e = 0; e < 8; e++) al[e] = arow[wm * 32 + i * 16 + rowmap[e]];
#pragma unroll
                for (int n = 0; n < 4; n++)
#pragma unroll
                    for (int e = 0; e < 8; e++) oacc[i][n].x[e] *= al[e];
            }
#pragma unroll
            for (int kk = 0; kk < 64; kk += 8) {
                wmma::fragment<wmma::matrix_a, 16, 16, 8, wmma::precision::tf32, wmma::row_major> a[2];
                wmma::fragment<wmma::matrix_b, 16, 16, 8, wmma::precision::tf32, wmma::row_major> bb[4];
#pragma unroll
                for (int i = 0; i < 2; i++)
                    wmma::load_matrix_sync(a[i], SP + (wm * 32 + i * 16) * 68 + kk, 68);
#pragma unroll
                for (int n = 0; n < 4; n++)
                    wmma::load_matrix_sync(bb[n], Vs + kk * 128 + wn * 64 + n * 16, 128);
#pragma unroll
                for (int i = 0; i < 2; i++)
#pragma unroll
                    for (int n = 0; n < 4; n++)
                        wmma::mma_sync(oacc[i][n], a[i], bb[n], oacc[i][n]);
            }
        }
        // no trailing sync: next iter's first sync protects SP/arow reuse
    }

    // store O to smem (reuse K buffers), write l into arow
#pragma unroll
    for (int i = 0; i < 2; i++)
#pragma unroll
        for (int n = 0; n < 4; n++)
            wmma::store_matrix_sync(Osm + (wm * 32 + i * 16) * 128 + wn * 64 + n * 16,
                                    oacc[i][n], 128, wmma::mem_row_major);
    __syncthreads();
    arow[r_sm] = l_state;   // both sub-threads write identical value

    // stage per-position v rows into Qs
    {
        float* Vf = Qs;
        const float* vg = vlin + ((size_t)(b * T + q0)) * (KVH * HD) + kvh * HD;
        for (int i = tid; i < 128 * 32; i += 256) {
            int r = i >> 5, c = i & 31;
            ((float4*)(Vf + r * 128))[c] = ((const float4*)(vg + (size_t)r * (KVH * HD)))[c];
        }
    }
    __syncthreads();

    // epilogue: /l, v-orthogonalize, transpose-store tf32 (2 threads per row)
    {
        const float* Vf = Qs;
        float invl = 1.0f / arow[r_sm];
        const float4* v4 = (const float4*)(Vf + r_sm * 128 + sub * 64);
        const float4* o4 = (const float4*)(Osm + r_sm * 128 + sub * 64);
        float sv2 = 0.f, dyv = 0.f;
#pragma unroll
        for (int cc = 0; cc < 16; cc++) {
            int c = (cc + r_sm) & 15;
            float4 vv = v4[c];
            float4 yy = o4[c];
            sv2 += vv.x * vv.x + vv.y * vv.y + vv.z * vv.z + vv.w * vv.w;
            dyv += yy.x * vv.x + yy.y * vv.y + yy.z * vv.z + yy.w * vv.w;
        }
        sv2 += __shfl_xor_sync(0xffffffffu, sv2, 1);
        dyv += __shfl_xor_sync(0xffffffffu, dyv, 1);
        float nm = fmaxf(sqrtf(sv2), 1e-12f);
        float coef = (dyv * invl) / (nm * nm);
        float4* out4 = (float4*)(Y + (((size_t)(b * T + q0 + r_sm)) * H + h) * HD + sub * 64);
#pragma unroll
        for (int cc = 0; cc < 16; cc++) {
            int c = (cc + r_sm) & 15;
            float4 vv = v4[c];
            float4 yy = o4[c];
            float4 o;
            o.x = to_tf32(yy.x * invl - coef * vv.x);
            o.y = to_tf32(yy.y * invl - coef * vv.y);
            o.z = to_tf32(yy.z * invl - coef * vv.z);
            o.w = to_tf32(yy.w * invl - coef * vv.w);
            out4[c] = o;
        }
    }
}

// ---------------- launch ----------------------------------------------------
extern "C" void kernel_launch(void* const* d_in, const int* in_sizes, int n_in,
                              void* d_out, int out_size)
{
    const float* x    = (const float*)d_in[0];
    const float* Wq   = (const float*)d_in[1];
    const float* Wk   = (const float*)d_in[2];
    const float* Wv   = (const float*)d_in[3];
    const float* Wp   = (const float*)d_in[4];
    const float* gain = (const float*)d_in[5];

    float *qlin, *klin, *vlin, *q, *k, *v, *y;
    float *xt, *wqt, *wkt, *wvt, *wpt;
    cudaGetSymbolAddress((void**)&qlin, g_qlin);
    cudaGetSymbolAddress((void**)&klin, g_klin);
    cudaGetSymbolAddress((void**)&vlin, g_vlin);
    cudaGetSymbolAddress((void**)&q, g_q);
    cudaGetSymbolAddress((void**)&k, g_k);
    cudaGetSymbolAddress((void**)&v, g_v);
    cudaGetSymbolAddress((void**)&y, g_y);
    cudaGetSymbolAddress((void**)&xt, g_xt);
    cudaGetSymbolAddress((void**)&wqt, g_wqt);
    cudaGetSymbolAddress((void**)&wkt, g_wkt);
    cudaGetSymbolAddress((void**)&wvt, g_wvt);
    cudaGetSymbolAddress((void**)&wpt, g_wpt);

    cudaFuncSetAttribute(gemm_tf32, cudaFuncAttributeMaxDynamicSharedMemorySize, 65536);
    cudaFuncSetAttribute(flash_kernel, cudaFuncAttributeMaxDynamicSharedMemorySize, FA_SMEM);

    // tf32 truncation of GEMM operands
    tf32_convert<<<(MTOT * DIM / 4) / 256, 256>>>(x, xt, MTOT * DIM / 4);
    tf32_convert<<<(DIM * DIM / 4) / 256, 256>>>(Wq, wqt, DIM * DIM / 4);
    tf32_convert<<<(KVH * HD * DIM / 4) / 256, 256>>>(Wk, wkt, KVH * HD * DIM / 4);
    tf32_convert<<<(KVH * HD * DIM / 4) / 256, 256>>>(Wv, wvt, KVH * HD * DIM / 4);
    tf32_convert<<<(DIM * DIM / 4) / 256, 256>>>(Wp, wpt, DIM * DIM / 4);

    // QKV projections
    gemm_tf32<<<dim3(DIM / 128, MTOT / 128), 256, 65536>>>(xt, wqt, qlin, MTOT, DIM, DIM);
    gemm_tf32<<<dim3((KVH * HD) / 128, MTOT / 128), 256, 65536>>>(xt, wkt, klin, MTOT, KVH * HD, DIM);
    gemm_tf32<<<dim3((KVH * HD) / 128, MTOT / 128), 256, 65536>>>(xt, wvt, vlin, MTOT, KVH * HD, DIM);

    // rms+rope (+gain+scale) and v reorder — all emit tf32
    rope_q_kernel<<<(BATCH * T * H) / 4, 128>>>(qlin, gain, q);
    rope_k_kernel<<<(BATCH * T * KVH) / 4, 128>>>(klin, k);
    v_reorder_kernel<<<(MTOT * KVH * HD / 4) / 256, 256>>>(vlin, v);

    // flash attention + fused epilogue (emits tf32 y)
    flash_kernel<<<dim3(T / 128, H, BATCH), 256, FA_SMEM>>>(q, k, v, vlin, y);

    // output projection
    gemm_tf32<<<dim3(DIM / 128, MTOT / 128), 256, 65536>>>(y, wpt, (float*)d_out, MTOT, DIM, DIM);
}

// round 4
// speedup vs baseline: 2.2379x; 1.5033x over previous
#include <cuda_runtime.h>
#include <cuda_bf16.h>
#include <mma.h>
#include <math.h>

using namespace nvcuda;

#define DIM 2048
#define H 16
#define KVH 4
#define HD 128
#define RD 64
#define BATCH 4
#define T 2048
#define MTOT (BATCH * T)   // 8192
#define SCALE 0.08838834764831845f
#define LOG2_10000 13.287712379549449f

// ---------------- scratch -----------------------------------------------------
__device__ float g_qlin[MTOT * DIM];
__device__ float g_klin[MTOT * KVH * HD];
__device__ float g_vlin[MTOT * KVH * HD];
__device__ float g_q[BATCH * H * T * HD];
__device__ float g_k[BATCH * KVH * T * HD];
__device__ float g_v[BATCH * KVH * T * HD];
__device__ float g_y[MTOT * DIM];
__device__ float g_xt[MTOT * DIM];
__device__ float g_wqt[DIM * DIM];
__device__ float g_wkt[KVH * HD * DIM];
__device__ float g_wvt[KVH * HD * DIM];
__device__ float g_wpt[DIM * DIM];

// ---------------- helpers ------------------------------------------------------
__device__ __forceinline__ float to_tf32(float x) {
    float r;
    asm("cvt.rna.tf32.f32 %0, %1;\n" : "=f"(r) : "f"(x));
    return r;
}
__device__ __forceinline__ void cp_async16(void* smem, const void* gmem) {
    unsigned s = (unsigned)__cvta_generic_to_shared(smem);
    asm volatile("cp.async.cg.shared.global [%0], [%1], 16;\n" :: "r"(s), "l"(gmem) : "memory");
}
#define CP_COMMIT asm volatile("cp.async.commit_group;\n" ::: "memory")
#define CP_WAIT0  asm volatile("cp.async.wait_group 0;\n" ::: "memory")
#define CP_WAIT1  asm volatile("cp.async.wait_group 1;\n" ::: "memory")
#define CP_WAIT2  asm volatile("cp.async.wait_group 2;\n" ::: "memory")

// ---------------- fused tf32 truncation of all GEMM operands ------------------
#define N4X 4194304
#define N4Q 1048576
#define N4K 262144
#define N4V 262144
#define N4P 1048576
__global__ void convert_all(
    const float* __restrict__ x, const float* __restrict__ wq,
    const float* __restrict__ wk, const float* __restrict__ wv,
    const float* __restrict__ wp,
    float* __restrict__ xt, float* __restrict__ wqt,
    float* __restrict__ wkt, float* __restrict__ wvt, float* __restrict__ wpt)
{
    int i = blockIdx.x * blockDim.x + threadIdx.x;
    const float4* src; float4* dst; int off;
    if (i < N4X)                         { src = (const float4*)x;  dst = (float4*)xt;  off = 0; }
    else if (i < N4X + N4Q)              { src = (const float4*)wq; dst = (float4*)wqt; off = N4X; }
    else if (i < N4X + N4Q + N4K)        { src = (const float4*)wk; dst = (float4*)wkt; off = N4X + N4Q; }
    else if (i < N4X + N4Q + N4K + N4V)  { src = (const float4*)wv; dst = (float4*)wvt; off = N4X + N4Q + N4K; }
    else                                 { src = (const float4*)wp; dst = (float4*)wpt; off = N4X + N4Q + N4K + N4V; }
    int j = i - off;
    float4 v = src[j];
    v.x = to_tf32(v.x); v.y = to_tf32(v.y);
    v.z = to_tf32(v.z); v.w = to_tf32(v.w);
    dst[j] = v;
}

// ---------------- TF32 GEMM, segmented N --------------------------------------
// C_seg[M, n_seg] = A[M,K] @ B_seg[n_seg,K]^T for up to 3 segments selected by bn.
// BM=BN=128, BK=32, 4 warps (64x64 each), 3-stage cp.async, smem pad 36.
#define GSTRIDE 36
#define GSTAGE (128 * GSTRIDE)            // floats per matrix per stage
#define GEMM_SMEM (3 * 2 * GSTAGE * 4)    // 110592 bytes

__global__ void __launch_bounds__(128, 2) gemm_seg(
    const float* __restrict__ A, int K,
    const float* __restrict__ B0, float* __restrict__ C0, int t0, int ldc0,
    const float* __restrict__ B1, float* __restrict__ C1, int t1, int ldc1,
    const float* __restrict__ B2, float* __restrict__ C2, int t2, int ldc2)
{
    extern __shared__ float smem[];
    const int tid = threadIdx.x;
    const int warp = tid >> 5;
    const int wr = warp >> 1, wc = warp & 1;
    const int bm = blockIdx.y;
    int bn = blockIdx.x;

    const float* B; float* C; int ldc;
    if (bn < t0)            { B = B0; C = C0; ldc = ldc0; }
    else if (bn < t0 + t1)  { B = B1; C = C1; ldc = ldc1; bn -= t0; }
    else                    { B = B2; C = C2; ldc = ldc2; bn -= t0 + t1; }

    const float* Ab = A + (size_t)bm * 128 * K;
    const float* Bb = B + (size_t)bn * 128 * K;

    wmma::fragment<wmma::accumulator, 16, 16, 8, float> acc[4][4];
#pragma unroll
    for (int i = 0; i < 4; i++)
#pragma unroll
        for (int j = 0; j < 4; j++) wmma::fill_fragment(acc[i][j], 0.0f);

    const int ntiles = K >> 5;
    // prologue: stages 0, 1
#pragma unroll
    for (int s = 0; s < 2; s++) {
        float* As = smem + s * 2 * GSTAGE;
        float* Bs = As + GSTAGE;
#pragma unroll
        for (int i = 0; i < 8; i++) {
            int idx = tid + i * 128;
            int r = idx >> 3, c = (idx & 7) * 4;
            cp_async16(As + r * GSTRIDE + c, Ab + (size_t)r * K + s * 32 + c);
            cp_async16(Bs + r * GSTRIDE + c, Bb + (size_t)r * K + s * 32 + c);
        }
        CP_COMMIT;
    }

    for (int kt = 0; kt < ntiles; kt++) {
        CP_WAIT1;
        __syncthreads();
        float* As = smem + (kt % 3) * 2 * GSTAGE;
        float* Bs = As + GSTAGE;
#pragma unroll
        for (int kk = 0; kk < 32; kk += 8) {
            wmma::fragment<wmma::matrix_a, 16, 16, 8, wmma::precision::tf32, wmma::row_major> a[4];
            wmma::fragment<wmma::matrix_b, 16, 16, 8, wmma::precision::tf32, wmma::col_major> bf[4];
#pragma unroll
            for (int i = 0; i < 4; i++)
                wmma::load_matrix_sync(a[i], As + (wr * 64 + i * 16) * GSTRIDE + kk, GSTRIDE);
#pragma unroll
            for (int j = 0; j < 4; j++)
                wmma::load_matrix_sync(bf[j], Bs + (wc * 64 + j * 16) * GSTRIDE + kk, GSTRIDE);
#pragma unroll
            for (int i = 0; i < 4; i++)
#pragma unroll
                for (int j = 0; j < 4; j++)
                    wmma::mma_sync(acc[i][j], a[i], bf[j], acc[i][j]);
        }
        __syncthreads();
        if (kt + 2 < ntiles) {
            int s = (kt + 2) % 3;
            int k0 = (kt + 2) * 32;
            float* An = smem + s * 2 * GSTAGE;
            float* Bn = An + GSTAGE;
#pragma unroll
            for (int i = 0; i < 8; i++) {
                int idx = tid + i * 128;
                int r = idx >> 3, c = (idx & 7) * 4;
                cp_async16(An + r * GSTRIDE + c, Ab + (size_t)r * K + k0 + c);
                cp_async16(Bn + r * GSTRIDE + c, Bb + (size_t)r * K + k0 + c);
            }
        }
        CP_COMMIT;   // may be empty — keeps group accounting uniform
    }

#pragma unroll
    for (int i = 0; i < 4; i++)
#pragma unroll
        for (int j = 0; j < 4; j++)
            wmma::store_matrix_sync(
                C + (size_t)(bm * 128 + wr * 64 + i * 16) * ldc + bn * 128 + wc * 64 + j * 16,
                acc[i][j], ldc, wmma::mem_row_major);
}

// ---------------- fused RMSNorm+RoPE (q,k) + v reorder, tf32 out --------------
#define NWQ (BATCH * T * H)      // 131072
#define NWK (BATCH * T * KVH)    // 32768
#define NWV (BATCH * T * KVH)    // 32768
__global__ void rope_fused(
    const float* __restrict__ qlin, const float* __restrict__ klin,
    const float* __restrict__ vlin, const float* __restrict__ gain,
    float* __restrict__ qout, float* __restrict__ kout, float* __restrict__ vout)
{
    int w = (blockIdx.x * blockDim.x + threadIdx.x) >> 5;
    int lane = threadIdx.x & 31;

    if (w < NWQ + NWK) {
        bool isq = (w < NWQ);
        int hh, t, b, nh;
        const float* src;
        if (isq) {
            nh = H;
            hh = w % H; t = (w / H) % T; b = w / (H * T);
            src = qlin + ((size_t)(b * T + t)) * DIM + hh * HD;
        } else {
            int wk = w - NWQ;
            nh = KVH;
            hh = wk % KVH; t = (wk / KVH) % T; b = wk / (KVH * T);
            src = klin + ((size_t)(b * T + t)) * (KVH * HD) + hh * HD;
        }
        float v0 = src[lane], v1 = src[lane + 32], v2 = src[lane + 64], v3 = src[lane + 96];
        float ss = v0 * v0 + v1 * v1 + v2 * v2 + v3 * v3;
#pragma unroll
        for (int o = 16; o; o >>= 1) ss += __shfl_xor_sync(0xffffffffu, ss, o);
        float r = rsqrtf(ss * (1.0f / 128.0f) + 1e-6f);
        v0 *= r; v1 *= r; v2 *= r; v3 *= r;

        float inv = exp2f(-(float)lane * (LOG2_10000 / 32.0f));
        float fr = (float)t * inv;
        float sn, cs;
        sincosf(fr, &sn, &cs);
        float o0 = v0 * cs - v1 * sn;
        float o1 = v1 * cs + v0 * sn;

        float g = isq ? gain[hh] * SCALE : 1.0f;
        float* dst = (isq ? qout : kout) + (((size_t)(b * nh + hh)) * T + t) * HD;
        dst[lane]      = to_tf32(o0 * g);
        dst[lane + 32] = to_tf32(o1 * g);
        dst[lane + 64] = to_tf32(v2 * g);
        dst[lane + 96] = to_tf32(v3 * g);
    } else {
        int u = w - NWQ - NWK;            // (bt, kv) unit
        int kv = u & 3;
        int bt = u >> 2;
        int t = bt & (T - 1);
        int b = bt >> 11;
        float4 val = ((const float4*)vlin)[u * 32 + lane];
        val.x = to_tf32(val.x); val.y = to_tf32(val.y);
        val.z = to_tf32(val.z); val.w = to_tf32(val.w);
        ((float4*)(vout + (((size_t)(b * KVH + kv)) * T + t) * HD))[lane] = val;
    }
}

// ---------------- Flash attention (BQ=128, BKV=64, 256 threads) ---------------
#define FA_SMEM 231936

__global__ void __launch_bounds__(256) flash_kernel(
    const float* __restrict__ Q, const float* __restrict__ Kg,
    const float* __restrict__ Vg, const float* __restrict__ vlin,
    float* __restrict__ Y)
{
    extern __shared__ char sm[];
    float* Qs   = (float*)sm;
    float* Ksm  = (float*)(sm + 65536);
    float* Vsm  = (float*)(sm + 131072);
    float* SP   = (float*)(sm + 196608);
    float* arow = (float*)(sm + 231424);
    float* Osm  = Ksm;

    const int tid = threadIdx.x;
    const int warp = tid >> 5;
    const int wm = warp >> 1, wn = warp & 1;
    const int qi = blockIdx.x, h = blockIdx.y, b = blockIdx.z;
    const int q0 = qi * 128;
    const int kvh = h >> 2;
    const int njt = 2 * qi + 2;

    const float* Qbase = Q + (((size_t)b * H + h) * T + q0) * HD;
    const float* Kbase = Kg + ((size_t)b * KVH + kvh) * T * HD;
    const float* Vbase = Vg + ((size_t)b * KVH + kvh) * T * HD;

#pragma unroll
    for (int i = 0; i < 8; i++)
        cp_async16((float4*)Ksm + tid + i * 256, (const float4*)Kbase + tid + i * 256);
    CP_COMMIT;
#pragma unroll
    for (int i = 0; i < 8; i++)
        cp_async16((float4*)Vsm + tid + i * 256, (const float4*)Vbase + tid + i * 256);
    CP_COMMIT;

    for (int i = tid; i < 4096; i += 256)
        ((float4*)Qs)[i] = ((const float4*)Qbase)[i];
    {
        int r = tid >> 4, c = tid & 15;
        SP[r * 68 + c] = (float)r;
    }
    __syncthreads();

    int rowmap[8];
    {
        wmma::fragment<wmma::accumulator, 16, 16, 8, float> probe;
        wmma::load_matrix_sync(probe, SP, 68, wmma::mem_row_major);
#pragma unroll
        for (int e = 0; e < 8; e++) rowmap[e] = (int)probe.x[e];
    }

    wmma::fragment<wmma::accumulator, 16, 16, 8, float> oacc[2][4];
#pragma unroll
    for (int i = 0; i < 2; i++)
#pragma unroll
        for (int n = 0; n < 4; n++) wmma::fill_fragment(oacc[i][n], 0.0f);

    const int r_sm = tid >> 1, sub = tid & 1;
    float m_state = -INFINITY, l_state = 0.f;

    for (int j = 0; j < njt; j++) {
        const int buf = j & 1;
        float* Ks = Ksm + buf * 8192;
        float* Vs = Vsm + buf * 8192;
        const int kbase = j * 64;

        if (j + 1 < njt) {
            float* Kn = Ksm + (buf ^ 1) * 8192;
            const float4* Kg4 = (const float4*)(Kbase + (size_t)(j + 1) * 8192);
#pragma unroll
            for (int i = 0; i < 8; i++)
                cp_async16((float4*)Kn + tid + i * 256, Kg4 + tid + i * 256);
            CP_COMMIT;
            CP_WAIT2;
        } else {
            CP_WAIT1;
        }
        __syncthreads();

        {
            wmma::fragment<wmma::accumulator, 16, 16, 8, float> sacc[2][2];
#pragma unroll
            for (int i = 0; i < 2; i++)
#pragma unroll
                for (int n = 0; n < 2; n++) wmma::fill_fragment(sacc[i][n], 0.0f);
#pragma unroll
            for (int kk = 0; kk < 128; kk += 8) {
                wmma::fragment<wmma::matrix_a, 16, 16, 8, wmma::precision::tf32, wmma::row_major> a[2];
                wmma::fragment<wmma::matrix_b, 16, 16, 8, wmma::precision::tf32, wmma::col_major> bb[2];
#pragma unroll
                for (int i = 0; i < 2; i++)
                    wmma::load_matrix_sync(a[i], Qs + (wm * 32 + i * 16) * 128 + kk, 128);
#pragma unroll
                for (int n = 0; n < 2; n++)
                    wmma::load_matrix_sync(bb[n], Ks + (wn * 32 + n * 16) * 128 + kk, 128);
#pragma unroll
                for (int i = 0; i < 2; i++)
#pragma unroll
                    for (int n = 0; n < 2; n++)
                        wmma::mma_sync(sacc[i][n], a[i], bb[n], sacc[i][n]);
            }
#pragma unroll
            for (int i = 0; i < 2; i++)
#pragma unroll
                for (int n = 0; n < 2; n++)
                    wmma::store_matrix_sync(SP + (wm * 32 + i * 16) * 68 + wn * 32 + n * 16,
                                            sacc[i][n], 68, wmma::mem_row_major);
        }
        __syncthreads();

        {
            float* srow = SP + r_sm * 68 + sub * 32;
            int lim = q0 + r_sm - kbase - sub * 32;
            float mx = -INFINITY;
#pragma unroll
            for (int c = 0; c < 32; c++)
                if (c <= lim) mx = fmaxf(mx, srow[c]);
            mx = fmaxf(mx, __shfl_xor_sync(0xffffffffu, mx, 1));
            float mnew = fmaxf(m_state, mx);
            float alpha = __expf(m_state - mnew);
            float sum = 0.f;
#pragma unroll
            for (int c = 0; c < 32; c++) {
                float p = (c <= lim) ? __expf(srow[c] - mnew) : 0.f;
                sum += p;
                srow[c] = to_tf32(p);
            }
            sum += __shfl_xor_sync(0xffffffffu, sum, 1);
            m_state = mnew;
            l_state = l_state * alpha + sum;
            if (sub == 0) arow[r_sm] = alpha;
        }
        __syncthreads();

        if (j + 1 < njt) {
            float* Vn = Vsm + (buf ^ 1) * 8192;
            const float4* Vg4 = (const float4*)(Vbase + (size_t)(j + 1) * 8192);
#pragma unroll
            for (int i = 0; i < 8; i++)
                cp_async16((float4*)Vn + tid + i * 256, Vg4 + tid + i * 256);
            CP_COMMIT;
            CP_WAIT2;
        } else {
            CP_WAIT0;
        }
        __syncthreads();

        {
#pragma unroll
            for (int i = 0; i < 2; i++) {
                float al[8];
#pragma unroll
                for (int e = 0; e < 8; e++) al[e] = arow[wm * 32 + i * 16 + rowmap[e]];
#pragma unroll
                for (int n = 0; n < 4; n++)
#pragma unroll
                    for (int e = 0; e < 8; e++) oacc[i][n].x[e] *= al[e];
            }
#pragma unroll
            for (int kk = 0; kk < 64; kk += 8) {
                wmma::fragment<wmma::matrix_a, 16, 16, 8, wmma::precision::tf32, wmma::row_major> a[2];
                wmma::fragment<wmma::matrix_b, 16, 16, 8, wmma::precision::tf32, wmma::row_major> bb[4];
#pragma unroll
                for (int i = 0; i < 2; i++)
                    wmma::load_matrix_sync(a[i], SP + (wm * 32 + i * 16) * 68 + kk, 68);
#pragma unroll
                for (int n = 0; n < 4; n++)
                    wmma::load_matrix_sync(bb[n], Vs + kk * 128 + wn * 64 + n * 16, 128);
#pragma unroll
                for (int i = 0; i < 2; i++)
#pragma unroll
                    for (int n = 0; n < 4; n++)
                        wmma::mma_sync(oacc[i][n], a[i], bb[n], oacc[i][n]);
            }
        }
    }

#pragma unroll
    for (int i = 0; i < 2; i++)
#pragma unroll
        for (int n = 0; n < 4; n++)
            wmma::store_matrix_sync(Osm + (wm * 32 + i * 16) * 128 + wn * 64 + n * 16,
                                    oacc[i][n], 128, wmma::mem_row_major);
    __syncthreads();
    arow[r_sm] = l_state;

    {
        float* Vf = Qs;
        const float* vg = vlin + ((size_t)(b * T + q0)) * (KVH * HD) + kvh * HD;
        for (int i = tid; i < 128 * 32; i += 256) {
            int r = i >> 5, c = i & 31;
            ((float4*)(Vf + r * 128))[c] = ((const float4*)(vg + (size_t)r * (KVH * HD)))[c];
        }
    }
    __syncthreads();

    {
        const float* Vf = Qs;
        float invl = 1.0f / arow[r_sm];
        const float4* v4 = (const float4*)(Vf + r_sm * 128 + sub * 64);
        const float4* o4 = (const float4*)(Osm + r_sm * 128 + sub * 64);
        float sv2 = 0.f, dyv = 0.f;
#pragma unroll
        for (int cc = 0; cc < 16; cc++) {
            int c = (cc + r_sm) & 15;
            float4 vv = v4[c];
            float4 yy = o4[c];
            sv2 += vv.x * vv.x + vv.y * vv.y + vv.z * vv.z + vv.w * vv.w;
            dyv += yy.x * vv.x + yy.y * vv.y + yy.z * vv.z + yy.w * vv.w;
        }
        sv2 += __shfl_xor_sync(0xffffffffu, sv2, 1);
        dyv += __shfl_xor_sync(0xffffffffu, dyv, 1);
        float nm = fmaxf(sqrtf(sv2), 1e-12f);
        float coef = (dyv * invl) / (nm * nm);
        float4* out4 = (float4*)(Y + (((size_t)(b * T + q0 + r_sm)) * H + h) * HD + sub * 64);
#pragma unroll
        for (int cc = 0; cc < 16; cc++) {
            int c = (cc + r_sm) & 15;
            float4 vv = v4[c];
            float4 yy = o4[c];
            float4 o;
            o.x = to_tf32(yy.x * invl - coef * vv.x);
            o.y = to_tf32(yy.y * invl - coef * vv.y);
            o.z = to_tf32(yy.z * invl - coef * vv.z);
            o.w = to_tf32(yy.w * invl - coef * vv.w);
            out4[c] = o;
        }
    }
}

// ---------------- launch -------------------------------------------------------
extern "C" void kernel_launch(void* const* d_in, const int* in_sizes, int n_in,
                              void* d_out, int out_size)
{
    const float* x    = (const float*)d_in[0];
    const float* Wq   = (const float*)d_in[1];
    const float* Wk   = (const float*)d_in[2];
    const float* Wv   = (const float*)d_in[3];
    const float* Wp   = (const float*)d_in[4];
    const float* gain = (const float*)d_in[5];

    float *qlin, *klin, *vlin, *q, *k, *v, *y;
    float *xt, *wqt, *wkt, *wvt, *wpt;
    cudaGetSymbolAddress((void**)&qlin, g_qlin);
    cudaGetSymbolAddress((void**)&klin, g_klin);
    cudaGetSymbolAddress((void**)&vlin, g_vlin);
    cudaGetSymbolAddress((void**)&q, g_q);
    cudaGetSymbolAddress((void**)&k, g_k);
    cudaGetSymbolAddress((void**)&v, g_v);
    cudaGetSymbolAddress((void**)&y, g_y);
    cudaGetSymbolAddress((void**)&xt, g_xt);
    cudaGetSymbolAddress((void**)&wqt, g_wqt);
    cudaGetSymbolAddress((void**)&wkt, g_wkt);
    cudaGetSymbolAddress((void**)&wvt, g_wvt);
    cudaGetSymbolAddress((void**)&wpt, g_wpt);

    cudaFuncSetAttribute(gemm_seg, cudaFuncAttributeMaxDynamicSharedMemorySize, GEMM_SMEM);
    cudaFuncSetAttribute(flash_kernel, cudaFuncAttributeMaxDynamicSharedMemorySize, FA_SMEM);

    // 0: fused tf32 truncation
    convert_all<<<(N4X + N4Q + N4K + N4V + N4P) / 256, 256>>>(
        x, Wq, Wk, Wv, Wp, xt, wqt, wkt, wvt, wpt);

    // 1: fused QKV projection (N = 2048 + 512 + 512)
    gemm_seg<<<dim3(24, MTOT / 128), 128, GEMM_SMEM>>>(
        xt, DIM,
        wqt, qlin, 16, DIM,
        wkt, klin, 4, KVH * HD,
        wvt, vlin, 4, KVH * HD);

    // 2: fused rms+rope (q,k) + v reorder
    rope_fused<<<(NWQ + NWK + NWV) / 4, 128>>>(qlin, klin, vlin, gain, q, k, v);

    // 3: flash attention + fused epilogue   (profiled launch)
    flash_kernel<<<dim3(T / 128, H, BATCH), 256, FA_SMEM>>>(q, k, v, vlin, y);

    // 4: output projection
    gemm_seg<<<dim3(16, MTOT / 128), 128, GEMM_SMEM>>>(
        y, DIM,
        wpt, (float*)d_out, 16, DIM,
        wpt, (float*)d_out, 0, DIM,
        wpt, (float*)d_out, 0, DIM);
}